// round 16
// baseline (speedup 1.0000x reference)
#include <cuda_runtime.h>
#include <math_constants.h>

// Problem constants (B=2, H=16, S=2048, D=64)
#define S_LEN 2048
#define D_DIM 64
#define BH    32
#define BQ    128             // CTA tile: 128 q-rows x 128 k-cols
#define NTQ   (S_LEN / BQ)    // 16 tiles
#define PQ    132             // pitch (floats) for Qs/Ks/Ps
#define PVP   68              // pitch (floats) for Vs
#define NTHREADS 512

// smem layout (floats)
#define SM_KS (64 * PQ)
#define SM_VS (SM_KS + 64 * PQ)
#define SM_PS (SM_VS + 128 * PVP)
#define SM_MH (SM_PS + 128 * PQ)
#define SMEM_FLOATS (SM_MH + NTQ * BQ)
#define SMEM_BYTES  (SMEM_FLOATS * 4)   // 178176 bytes

typedef unsigned long long u64;

// ---------- packed f32x2 helpers (Blackwell sm_103a) ----------
__device__ __forceinline__ u64 pk(float lo, float hi) {
    u64 r; asm("mov.b64 %0, {%1,%2};" : "=l"(r) : "f"(lo), "f"(hi)); return r;
}
__device__ __forceinline__ void upk(u64 v, float& lo, float& hi) {
    asm("mov.b64 {%0,%1}, %2;" : "=f"(lo), "=f"(hi) : "l"(v));
}
__device__ __forceinline__ u64 ffma2(u64 a, u64 b, u64 c) {
    u64 d; asm("fma.rn.f32x2 %0, %1, %2, %3;" : "=l"(d) : "l"(a), "l"(b), "l"(c)); return d;
}
__device__ __forceinline__ u64 fmul2(u64 a, u64 b) {
    u64 d; asm("mul.rn.f32x2 %0, %1, %2;" : "=l"(d) : "l"(a), "l"(b)); return d;
}

// 128x64 gmem tile -> d-major smem (transposed), 2-bit XOR row-block swizzle.
// sm[d*PQ + ((row>>3 ^ ((d>>2)&3))<<3) + (row&7)], optional scale folded in.
template <bool SCALE>
__device__ __forceinline__ void load_tileT(const float* __restrict__ g, float* smp, int tid) {
#pragma unroll
    for (int it = 0; it < 4; it++) {
        int idx = tid + NTHREADS * it;
        int row = idx >> 4;
        int dq  = (idx & 15) << 2;
        float4 v = *(const float4*)(g + row * D_DIM + dq);
        if (SCALE) { v.x *= 0.125f; v.y *= 0.125f; v.z *= 0.125f; v.w *= 0.125f; }
        int key  = (dq >> 2) & 3;
        int base = (((row >> 3) ^ key) << 3) + (row & 7);
        smp[(dq + 0) * PQ + base] = v.x;
        smp[(dq + 1) * PQ + base] = v.y;
        smp[(dq + 2) * PQ + base] = v.z;
        smp[(dq + 3) * PQ + base] = v.w;
    }
}

// 128x64 gmem tile -> row-major smem, 3-bit XOR col-block swizzle.
__device__ __forceinline__ void load_tileV(const float* __restrict__ g, float* smp, int tid) {
#pragma unroll
    for (int it = 0; it < 4; it++) {
        int idx = tid + NTHREADS * it;
        int row = idx >> 4;
        int dq  = (idx & 15) << 2;
        float4 v = *(const float4*)(g + row * D_DIM + dq);
        int phys = ((((dq >> 3) ^ (row & 7))) << 3) + (dq & 7);
        *(float4*)(smp + row * PVP + phys) = v;
    }
}

__global__ void __launch_bounds__(NTHREADS, 1)
sdpa_causal_kernel(const float* __restrict__ Qg, const float* __restrict__ Kg,
                   const float* __restrict__ Vg, float* __restrict__ Og,
                   float* __restrict__ Wg)
{
    extern __shared__ float sm[];
    float* Qs = sm;                 // [64][PQ] d-major, swizzled, pre-scaled by 0.125
    float* Ks = sm + SM_KS;         // [64][PQ] d-major, swizzled
    float* Vs = sm + SM_VS;         // [128][PVP] j-major, swizzled (also O-combine scratch)
    float* Ps = sm + SM_PS;         // [128][PQ] j-major (p transposed), swizzled
    float* mh = sm + SM_MH;         // [NTQ][BQ] running-max history

    const int qt  = (NTQ - 1) - blockIdx.x;   // heavy tiles first (LPT)
    const int bh  = blockIdx.y;
    const int tid = threadIdx.x;
    const int tr  = tid >> 4;                 // 0..31 -> q-row group (4 rows)
    const int tc  = tid & 15;                 // 0..15 -> col group
    const int i0  = tr * 4;
    const int jA  = tc * 4;
    const int jB  = 64 + jA;
    const int aoff = ((tr >> 1) << 3) + ((tr & 1) << 2);   // pre-xor row offset parts
    const int koff = ((tc >> 1) << 3) + ((tc & 1) << 2);

    const float* Qb = Qg + (size_t)bh * S_LEN * D_DIM + (size_t)qt * BQ * D_DIM;
    const float* Kb = Kg + (size_t)bh * S_LEN * D_DIM;
    const float* Vb = Vg + (size_t)bh * S_LEN * D_DIM;
    float*       Ob = Og + (size_t)bh * S_LEN * D_DIM + (size_t)qt * BQ * D_DIM;
    float*       Wb = Wg + (size_t)bh * S_LEN * S_LEN;

    load_tileT<true>(Qb, Qs, tid);

    float m_r[4], l_r[4];
#pragma unroll
    for (int r = 0; r < 4; r++) { m_r[r] = -CUDART_INF_F; l_r[r] = 0.f; }

    // PV: j-half split, 8 dd per thread, packed over dd-pairs
    const int jbase = (tc >> 3) << 6;         // 0 or 64
    const int dd0   = (tc & 7) << 3;          // 0..56

    u64 Oac[4][4];                            // [row][ddpair]
#pragma unroll
    for (int r = 0; r < 4; r++)
#pragma unroll
        for (int c = 0; c < 4; c++) Oac[r][c] = 0ull;

    for (int jt = 0; jt <= qt; jt++) {
        __syncthreads();                      // prev PV done with Ks/Vs/Ps
        load_tileT<false>(Kb + (size_t)jt * BQ * D_DIM, Ks, tid);
        load_tileV(Vb + (size_t)jt * BQ * D_DIM, Vs, tid);
        __syncthreads();

        // ---------------- QK^T: 4x8 micro-tile, acc packed over col-pairs ----------------
        u64 acc[4][4];                        // [row][colpair]: (jA,jA+1)(jA+2,jA+3)(jB,jB+1)(jB+2,jB+3)
#pragma unroll
        for (int r = 0; r < 4; r++)
#pragma unroll
            for (int c = 0; c < 4; c++) acc[r][c] = 0ull;

#pragma unroll 4
        for (int d = 0; d < D_DIM; d++) {
            int key = (d >> 2) & 3;
            int kx  = key << 3;
            float4 a = *(const float4*)(Qs + d * PQ + (aoff ^ kx));   // Q rows i0..i0+3
            const float* krow = Ks + d * PQ + (koff ^ kx);
            ulonglong2 bA = *(const ulonglong2*)krow;                  // cols jA..jA+3
            ulonglong2 bB = *(const ulonglong2*)(krow + 64);           // cols jB..jB+3
            u64 a0 = pk(a.x, a.x), a1 = pk(a.y, a.y), a2 = pk(a.z, a.z), a3 = pk(a.w, a.w);
            acc[0][0] = ffma2(a0, bA.x, acc[0][0]);
            acc[0][1] = ffma2(a0, bA.y, acc[0][1]);
            acc[0][2] = ffma2(a0, bB.x, acc[0][2]);
            acc[0][3] = ffma2(a0, bB.y, acc[0][3]);
            acc[1][0] = ffma2(a1, bA.x, acc[1][0]);
            acc[1][1] = ffma2(a1, bA.y, acc[1][1]);
            acc[1][2] = ffma2(a1, bB.x, acc[1][2]);
            acc[1][3] = ffma2(a1, bB.y, acc[1][3]);
            acc[2][0] = ffma2(a2, bA.x, acc[2][0]);
            acc[2][1] = ffma2(a2, bA.y, acc[2][1]);
            acc[2][2] = ffma2(a2, bB.x, acc[2][2]);
            acc[2][3] = ffma2(a2, bB.y, acc[2][3]);
            acc[3][0] = ffma2(a3, bA.x, acc[3][0]);
            acc[3][1] = ffma2(a3, bA.y, acc[3][1]);
            acc[3][2] = ffma2(a3, bB.x, acc[3][2]);
            acc[3][3] = ffma2(a3, bB.y, acc[3][3]);
        }

        // unpack (scale already folded into Q)
        float p[4][8];
#pragma unroll
        for (int r = 0; r < 4; r++) {
            upk(acc[r][0], p[r][0], p[r][1]);
            upk(acc[r][1], p[r][2], p[r][3]);
            upk(acc[r][2], p[r][4], p[r][5]);
            upk(acc[r][3], p[r][6], p[r][7]);
        }

        // causal mask on diagonal tile
        if (jt == qt) {
#pragma unroll
            for (int r = 0; r < 4; r++)
#pragma unroll
                for (int c = 0; c < 8; c++) {
                    int col = (c < 4) ? (jA + c) : (jB + c - 4);
                    if (col > i0 + r) p[r][c] = -CUDART_INF_F;
                }
        }

        // ---------------- online softmax ----------------
        float mnew[4], alpha[4];
#pragma unroll
        for (int r = 0; r < 4; r++) {
            float tm = p[r][0];
#pragma unroll
            for (int c = 1; c < 8; c++) tm = fmaxf(tm, p[r][c]);
#pragma unroll
            for (int off = 1; off < 16; off <<= 1)
                tm = fmaxf(tm, __shfl_xor_sync(0xffffffffu, tm, off));
            mnew[r]  = fmaxf(m_r[r], tm);
            alpha[r] = __expf(m_r[r] - mnew[r]);
            float rs = 0.f;
#pragma unroll
            for (int c = 0; c < 8; c++) { p[r][c] = __expf(p[r][c] - mnew[r]); rs += p[r][c]; }
#pragma unroll
            for (int off = 1; off < 16; off <<= 1)
                rs += __shfl_xor_sync(0xffffffffu, rs, off);
            l_r[r] = l_r[r] * alpha[r] + rs;
            m_r[r] = mnew[r];
        }
#pragma unroll
        for (int r = 0; r < 4; r++) {
            u64 av = pk(alpha[r], alpha[r]);
            Oac[r][0] = fmul2(av, Oac[r][0]);
            Oac[r][1] = fmul2(av, Oac[r][1]);
            Oac[r][2] = fmul2(av, Oac[r][2]);
            Oac[r][3] = fmul2(av, Oac[r][3]);
        }

        if (tc == 0) {
#pragma unroll
            for (int r = 0; r < 4; r++) mh[jt * BQ + i0 + r] = mnew[r];
        }

        // stash p transposed (j-major, swizzled) for PV
        {
            int poff = aoff ^ ((tc & 3) << 3);     // key for cols jA..jA+3 and jB..jB+3 is tc&3
#pragma unroll
            for (int cc = 0; cc < 4; cc++) {
                *(float4*)(Ps + (jA + cc) * PQ + poff) =
                    make_float4(p[0][cc], p[1][cc], p[2][cc], p[3][cc]);
                *(float4*)(Ps + (jB + cc) * PQ + poff) =
                    make_float4(p[0][cc+4], p[1][cc+4], p[2][cc+4], p[3][cc+4]);
            }
        }

        // write UNNORMALIZED p for non-diagonal tiles (fixed up in epilogue)
        if (jt < qt) {
#pragma unroll
            for (int r = 0; r < 4; r++) {
                float* wrow = Wb + (size_t)(qt * BQ + i0 + r) * S_LEN + jt * BQ;
                *(float4*)(wrow + jA) = make_float4(p[r][0], p[r][1], p[r][2], p[r][3]);
                *(float4*)(wrow + jB) = make_float4(p[r][4], p[r][5], p[r][6], p[r][7]);
            }
        }

        __syncthreads();   // Ps visible

        // ---------------- PV: j-half split, Oac packed over dd-pairs ----------------
#pragma unroll 4
        for (int jj = 0; jj < 64; jj++) {
            int j = jbase + jj;
            int kx = ((jj >> 2) & 3) << 3;                 // (j>>2)&3 == (jj>>2)&3 (jbase mult of 64)
            float4 a = *(const float4*)(Ps + j * PQ + (aoff ^ kx));  // p[i0..i0+3][j]
            const float* vrow = Vs + j * PVP + ((((tc & 7) ^ (j & 7))) << 3);
            ulonglong2 b0 = *(const ulonglong2*)vrow;       // dd0..dd0+3
            ulonglong2 b1 = *(const ulonglong2*)(vrow + 4); // dd0+4..dd0+7
            u64 a0 = pk(a.x, a.x), a1 = pk(a.y, a.y), a2 = pk(a.z, a.z), a3 = pk(a.w, a.w);
            Oac[0][0] = ffma2(a0, b0.x, Oac[0][0]);
            Oac[0][1] = ffma2(a0, b0.y, Oac[0][1]);
            Oac[0][2] = ffma2(a0, b1.x, Oac[0][2]);
            Oac[0][3] = ffma2(a0, b1.y, Oac[0][3]);
            Oac[1][0] = ffma2(a1, b0.x, Oac[1][0]);
            Oac[1][1] = ffma2(a1, b0.y, Oac[1][1]);
            Oac[1][2] = ffma2(a1, b1.x, Oac[1][2]);
            Oac[1][3] = ffma2(a1, b1.y, Oac[1][3]);
            Oac[2][0] = ffma2(a2, b0.x, Oac[2][0]);
            Oac[2][1] = ffma2(a2, b0.y, Oac[2][1]);
            Oac[2][2] = ffma2(a2, b1.x, Oac[2][2]);
            Oac[2][3] = ffma2(a2, b1.y, Oac[2][3]);
            Oac[3][0] = ffma2(a3, b0.x, Oac[3][0]);
            Oac[3][1] = ffma2(a3, b0.y, Oac[3][1]);
            Oac[3][2] = ffma2(a3, b1.x, Oac[3][2]);
            Oac[3][3] = ffma2(a3, b1.y, Oac[3][3]);
        }
    }

    float invl[4];
#pragma unroll
    for (int r = 0; r < 4; r++) invl[r] = 1.0f / l_r[r];

    // diagonal W tile: re-read p of the last (jt==qt) tile from Ps; m there == m_final -> /l
    {
        int poff = aoff ^ ((tc & 3) << 3);
        float cA[4][4], cB[4][4];
#pragma unroll
        for (int cc = 0; cc < 4; cc++) {
            float4 u = *(const float4*)(Ps + (jA + cc) * PQ + poff);
            cA[cc][0] = u.x; cA[cc][1] = u.y; cA[cc][2] = u.z; cA[cc][3] = u.w;
            float4 v = *(const float4*)(Ps + (jB + cc) * PQ + poff);
            cB[cc][0] = v.x; cB[cc][1] = v.y; cB[cc][2] = v.z; cB[cc][3] = v.w;
        }
#pragma unroll
        for (int r = 0; r < 4; r++) {
            float* wrow = Wb + (size_t)(qt * BQ + i0 + r) * S_LEN + qt * BQ;
            *(float4*)(wrow + jA) = make_float4(cA[0][r]*invl[r], cA[1][r]*invl[r],
                                                cA[2][r]*invl[r], cA[3][r]*invl[r]);
            *(float4*)(wrow + jB) = make_float4(cB[0][r]*invl[r], cB[1][r]*invl[r],
                                                cB[2][r]*invl[r], cB[3][r]*invl[r]);
        }
    }

    // ---------------- combine O partials across j-halves (Vs as scratch) ----------------
    __syncthreads();
    if (tc >= 8) {
#pragma unroll
        for (int r = 0; r < 4; r++) {
            float o[8];
            upk(Oac[r][0], o[0], o[1]);
            upk(Oac[r][1], o[2], o[3]);
            upk(Oac[r][2], o[4], o[5]);
            upk(Oac[r][3], o[6], o[7]);
            float* s = Vs + (i0 + r) * PVP + dd0;
            *(float4*)s       = make_float4(o[0], o[1], o[2], o[3]);
            *(float4*)(s + 4) = make_float4(o[4], o[5], o[6], o[7]);
        }
    }
    __syncthreads();
    if (tc < 8) {
#pragma unroll
        for (int r = 0; r < 4; r++) {
            float o[8];
            upk(Oac[r][0], o[0], o[1]);
            upk(Oac[r][1], o[2], o[3]);
            upk(Oac[r][2], o[4], o[5]);
            upk(Oac[r][3], o[6], o[7]);
            const float* s = Vs + (i0 + r) * PVP + dd0;
            float4 q0 = *(const float4*)s, q1 = *(const float4*)(s + 4);
            float il = invl[r];
            *(float4*)(Ob + (i0 + r) * D_DIM + dd0) =
                make_float4((o[0]+q0.x)*il, (o[1]+q0.y)*il, (o[2]+q0.z)*il, (o[3]+q0.w)*il);
            *(float4*)(Ob + (i0 + r) * D_DIM + dd0 + 4) =
                make_float4((o[4]+q1.x)*il, (o[5]+q1.y)*il, (o[6]+q1.z)*il, (o[7]+q1.w)*il);
        }
    }

    // ---------------- W fixup: rescale earlier tiles by exp(m_tile - m_final)/l ----------------
    for (int jt = 0; jt < qt; jt++) {
#pragma unroll
        for (int r = 0; r < 4; r++) {
            float f = __expf(mh[jt * BQ + i0 + r] - m_r[r]) * invl[r];
            float* wrow = Wb + (size_t)(qt * BQ + i0 + r) * S_LEN + jt * BQ;
            float4 w0 = *(float4*)(wrow + jA);
            float4 w1 = *(float4*)(wrow + jB);
            w0.x *= f; w0.y *= f; w0.z *= f; w0.w *= f;
            w1.x *= f; w1.y *= f; w1.z *= f; w1.w *= f;
            *(float4*)(wrow + jA) = w0;
            *(float4*)(wrow + jB) = w1;
        }
    }

    // ---------------- zero-fill strict upper-triangle tiles ----------------
    float4 z = make_float4(0.f, 0.f, 0.f, 0.f);
    for (int jt = qt + 1; jt < NTQ; jt++) {
#pragma unroll
        for (int r = 0; r < 4; r++) {
            float* wrow = Wb + (size_t)(qt * BQ + i0 + r) * S_LEN + jt * BQ;
            *(float4*)(wrow + jA) = z;
            *(float4*)(wrow + jB) = z;
        }
    }
}

extern "C" void kernel_launch(void* const* d_in, const int* in_sizes, int n_in,
                              void* d_out, int out_size) {
    (void)in_sizes; (void)n_in; (void)out_size;
    const float* q = (const float*)d_in[0];
    const float* k = (const float*)d_in[1];
    const float* v = (const float*)d_in[2];
    // d_in[3] is the mask (tril ones) — causal structure applied analytically.

    float* out = (float*)d_out;
    float* Og  = out;                                   // [B,H,S,D]
    float* Wg  = out + (size_t)BH * S_LEN * D_DIM;      // [B,H,S,S]

    cudaFuncSetAttribute(sdpa_causal_kernel,
                         cudaFuncAttributeMaxDynamicSharedMemorySize, SMEM_BYTES);

    dim3 grid(NTQ, BH);
    sdpa_causal_kernel<<<grid, NTHREADS, SMEM_BYTES>>>(q, k, v, Og, Wg);
}

// round 17
// speedup vs baseline: 1.2531x; 1.2531x over previous
#include <cuda_runtime.h>
#include <math_constants.h>

// Problem constants (B=2, H=16, S=2048, D=64)
#define S_LEN 2048
#define D_DIM 64
#define BH    32
#define BQ    128             // CTA tile: 128 q-rows x 128 k-cols
#define NTQ   (S_LEN / BQ)    // 16 tiles
#define PQ    132             // pitch (floats) for Qs/Ks/Ps
#define PVP   68              // pitch (floats) for Vs
#define NTHREADS 256

// smem layout (floats)
#define SM_QS  0
#define SM_KS0 (64 * PQ)
#define SM_KS1 (SM_KS0 + 64 * PQ)
#define SM_VS  (SM_KS1 + 64 * PQ)
#define SM_PS  (SM_VS + 128 * PVP)
#define SM_MH  (SM_PS + 128 * PQ)
#define SMEM_FLOATS (SM_MH + NTQ * BQ)
#define SMEM_BYTES  (SMEM_FLOATS * 4)   // 211968 bytes

typedef unsigned long long u64;

// K transposed scratch: KT[bh][d][s]  (16 MB)
__device__ float KTg[(size_t)BH * D_DIM * S_LEN];

// ---------- packed f32x2 helpers (Blackwell sm_103a) ----------
__device__ __forceinline__ u64 pk(float lo, float hi) {
    u64 r; asm("mov.b64 %0, {%1,%2};" : "=l"(r) : "f"(lo), "f"(hi)); return r;
}
__device__ __forceinline__ void upk(u64 v, float& lo, float& hi) {
    asm("mov.b64 {%0,%1}, %2;" : "=f"(lo), "=f"(hi) : "l"(v));
}
__device__ __forceinline__ u64 ffma2(u64 a, u64 b, u64 c) {
    u64 d; asm("fma.rn.f32x2 %0, %1, %2, %3;" : "=l"(d) : "l"(a), "l"(b), "l"(c)); return d;
}
__device__ __forceinline__ u64 fmul2(u64 a, u64 b) {
    u64 d; asm("mul.rn.f32x2 %0, %1, %2;" : "=l"(d) : "l"(a), "l"(b)); return d;
}

// ---------- cp.async helpers ----------
__device__ __forceinline__ void cpa16(unsigned saddr, const void* g) {
    asm volatile("cp.async.cg.shared.global [%0], [%1], 16;" :: "r"(saddr), "l"(g));
}
#define CPA_COMMIT() asm volatile("cp.async.commit_group;" ::: "memory")
#define CPA_WAIT0()  asm volatile("cp.async.wait_group 0;" ::: "memory")

// 128x64 gmem tile -> d-major smem (transposed), 2-bit XOR row-block swizzle,
// scale 0.125 folded in. Used once per CTA for Q.
__device__ __forceinline__ void load_tileT_q(const float* __restrict__ g, float* smp, int tid) {
#pragma unroll
    for (int it = 0; it < 8; it++) {
        int idx = tid + NTHREADS * it;
        int row = idx >> 4;
        int dq  = (idx & 15) << 2;
        float4 v = *(const float4*)(g + row * D_DIM + dq);
        v.x *= 0.125f; v.y *= 0.125f; v.z *= 0.125f; v.w *= 0.125f;
        int key  = (dq >> 2) & 3;
        int base = (((row >> 3) ^ key) << 3) + (row & 7);
        smp[(dq + 0) * PQ + base] = v.x;
        smp[(dq + 1) * PQ + base] = v.y;
        smp[(dq + 2) * PQ + base] = v.z;
        smp[(dq + 3) * PQ + base] = v.w;
    }
}

// K tile (already transposed in gmem: KT row d is s-contiguous) -> d-major smem via cp.async.
// gKT points at KT[bh] + jt*BQ (column offset).
__device__ __forceinline__ void cpasync_K(const float* __restrict__ gKT, unsigned sKs, int tid) {
#pragma unroll
    for (int it = 0; it < 8; it++) {
        int idx = tid + NTHREADS * it;       // 2048 16B-chunks
        int d   = idx >> 5;                  // 32 chunks per d-row
        int jq  = (idx & 31) << 2;
        int key = (d >> 2) & 3;
        int swz = (((jq >> 3) ^ key) << 3) + (jq & 7);
        cpa16(sKs + (unsigned)(d * PQ + swz) * 4u, gKT + (size_t)d * S_LEN + jq);
    }
}

// V tile (row-major gmem) -> row-major smem with 3-bit XOR col-block swizzle via cp.async.
__device__ __forceinline__ void cpasync_V(const float* __restrict__ gV, unsigned sVs, int tid) {
#pragma unroll
    for (int it = 0; it < 8; it++) {
        int idx = tid + NTHREADS * it;
        int row = idx >> 4;
        int dq  = (idx & 15) << 2;
        int phys = (((dq >> 3) ^ (row & 7)) << 3) + (dq & 7);
        cpa16(sVs + (unsigned)(row * PVP + phys) * 4u, gV + row * D_DIM + dq);
    }
}

// ---------------- K transpose pre-pass ----------------
__global__ void __launch_bounds__(256, 8)
transpose_k_kernel(const float* __restrict__ Kg) {
    __shared__ float t[32][33];
    int bh = blockIdx.z;
    int s0 = blockIdx.x * 32;
    int d0 = blockIdx.y * 32;
    int x = threadIdx.x & 31;
    int y = threadIdx.x >> 5;           // 0..7
    const float* src = Kg + (size_t)bh * S_LEN * D_DIM;
#pragma unroll
    for (int i = 0; i < 32; i += 8)
        t[y + i][x] = src[(size_t)(s0 + y + i) * D_DIM + d0 + x];
    __syncthreads();
    float* dst = KTg + (size_t)bh * D_DIM * S_LEN;
#pragma unroll
    for (int i = 0; i < 32; i += 8)
        dst[(size_t)(d0 + y + i) * S_LEN + s0 + x] = t[x][y + i];
}

// ---------------- main attention kernel ----------------
__global__ void __launch_bounds__(NTHREADS, 1)
sdpa_causal_kernel(const float* __restrict__ Qg, const float* __restrict__ Vg,
                   float* __restrict__ Og, float* __restrict__ Wg)
{
    extern __shared__ float sm[];
    float* Qs = sm + SM_QS;         // [64][PQ] d-major, swizzled, pre-scaled
    float* Vs = sm + SM_VS;         // [128][PVP] j-major, swizzled (also O-combine scratch)
    float* Ps = sm + SM_PS;         // [128][PQ] j-major (p transposed), swizzled
    float* mh = sm + SM_MH;         // [NTQ][BQ] running-max history
    unsigned smem_u32 = (unsigned)__cvta_generic_to_shared(sm);
    unsigned sKs[2] = { smem_u32 + SM_KS0 * 4u, smem_u32 + SM_KS1 * 4u };
    unsigned sVsA   = smem_u32 + SM_VS * 4u;

    const int qt  = (NTQ - 1) - blockIdx.x;   // heavy tiles first (LPT)
    const int bh  = blockIdx.y;
    const int tid = threadIdx.x;
    const int tr  = tid >> 4;                 // 0..15 -> q-row group (8 rows)
    const int tc  = tid & 15;                 // 0..15 -> col group
    const int i0  = tr * 8;
    const int jA  = tc * 4;
    const int jB  = 64 + jA;

    const float* Qb  = Qg + (size_t)bh * S_LEN * D_DIM + (size_t)qt * BQ * D_DIM;
    const float* KTb = KTg + (size_t)bh * D_DIM * S_LEN;
    const float* Vb  = Vg + (size_t)bh * S_LEN * D_DIM;
    float*       Ob  = Og + (size_t)bh * S_LEN * D_DIM + (size_t)qt * BQ * D_DIM;
    float*       Wb  = Wg + (size_t)bh * S_LEN * S_LEN;

    // prologue: K tile 0 via cp.async, Q via LDG+STS
    cpasync_K(KTb, sKs[0], tid);
    CPA_COMMIT();
    load_tileT_q(Qb, Qs, tid);
    CPA_WAIT0();
    __syncthreads();

    float m_r[8], l_r[8];
#pragma unroll
    for (int r = 0; r < 8; r++) { m_r[r] = -CUDART_INF_F; l_r[r] = 0.f; }

    u64 Oac[4][8];                            // 8 rows (pairs) x 8 dd, partial over j-half
#pragma unroll
    for (int rp = 0; rp < 4; rp++)
#pragma unroll
        for (int c = 0; c < 8; c++) Oac[rp][c] = 0ull;

    const int jbase = (tc >> 3) << 6;         // PV j-half: 0 or 64
    const int dd0   = (tc & 7) << 3;          // PV dd block

    float p[8][8];                            // exp(scores) of current tile

    for (int jt = 0; jt <= qt; jt++) {
        const int cur = jt & 1;
        const float* Ks = sm + (cur ? SM_KS1 : SM_KS0);

        // V(jt) load overlaps QK + softmax
        cpasync_V(Vb + (size_t)jt * BQ * D_DIM, sVsA, tid);
        CPA_COMMIT();

        // ---------------- QK^T: 8x8 micro-tile ----------------
        u64 acc[4][8];
#pragma unroll
        for (int rp = 0; rp < 4; rp++)
#pragma unroll
            for (int c = 0; c < 8; c++) acc[rp][c] = 0ull;

#pragma unroll 4
        for (int d = 0; d < D_DIM; d++) {
            int key = (d >> 2) & 3;
            const float* qrow = Qs + d * PQ + ((tr ^ key) << 3);
            ulonglong2 a01 = *(const ulonglong2*)qrow;        // rows i0..i0+3
            ulonglong2 a23 = *(const ulonglong2*)(qrow + 4);  // rows i0+4..i0+7
            const float* krow = Ks + d * PQ + ((((tc >> 1) ^ key)) << 3) + ((tc & 1) << 2);
            float4 b0 = *(const float4*)krow;                 // cols jA..jA+3
            float4 b1 = *(const float4*)(krow + 64);          // cols jB..jB+3
            u64 aa[4] = {a01.x, a01.y, a23.x, a23.y};
            u64 bb[8] = {pk(b0.x,b0.x), pk(b0.y,b0.y), pk(b0.z,b0.z), pk(b0.w,b0.w),
                         pk(b1.x,b1.x), pk(b1.y,b1.y), pk(b1.z,b1.z), pk(b1.w,b1.w)};
#pragma unroll
            for (int rp = 0; rp < 4; rp++)
#pragma unroll
                for (int c = 0; c < 8; c++)
                    acc[rp][c] = ffma2(aa[rp], bb[c], acc[rp][c]);
        }

        // unpack (scale folded into Q)
#pragma unroll
        for (int rp = 0; rp < 4; rp++)
#pragma unroll
            for (int c = 0; c < 8; c++)
                upk(acc[rp][c], p[2*rp][c], p[2*rp+1][c]);

        // causal mask on diagonal tile
        if (jt == qt) {
#pragma unroll
            for (int r = 0; r < 8; r++)
#pragma unroll
                for (int c = 0; c < 8; c++) {
                    int col = (c < 4) ? (jA + c) : (jB + c - 4);
                    if (col > i0 + r) p[r][c] = -CUDART_INF_F;
                }
        }

        // ---------------- online softmax ----------------
        float mnew[8], alpha[8];
#pragma unroll
        for (int r = 0; r < 8; r++) {
            float tm = p[r][0];
#pragma unroll
            for (int c = 1; c < 8; c++) tm = fmaxf(tm, p[r][c]);
#pragma unroll
            for (int off = 1; off < 16; off <<= 1)
                tm = fmaxf(tm, __shfl_xor_sync(0xffffffffu, tm, off));
            mnew[r]  = fmaxf(m_r[r], tm);
            alpha[r] = __expf(m_r[r] - mnew[r]);
            float rs = 0.f;
#pragma unroll
            for (int c = 0; c < 8; c++) { p[r][c] = __expf(p[r][c] - mnew[r]); rs += p[r][c]; }
#pragma unroll
            for (int off = 1; off < 16; off <<= 1)
                rs += __shfl_xor_sync(0xffffffffu, rs, off);
            l_r[r] = l_r[r] * alpha[r] + rs;
            m_r[r] = mnew[r];
        }
        {
            u64 av[4] = {pk(alpha[0],alpha[1]), pk(alpha[2],alpha[3]),
                         pk(alpha[4],alpha[5]), pk(alpha[6],alpha[7])};
#pragma unroll
            for (int rp = 0; rp < 4; rp++)
#pragma unroll
                for (int c = 0; c < 8; c++)
                    Oac[rp][c] = fmul2(av[rp], Oac[rp][c]);
        }

        if (tc == 0) {
#pragma unroll
            for (int r = 0; r < 8; r++) mh[jt * BQ + i0 + r] = mnew[r];
        }

        // stash p transposed (j-major, swizzled) for PV
#pragma unroll
        for (int cc = 0; cc < 4; cc++) {
            float* dst = Ps + (jA + cc) * PQ + ((tr ^ (tc & 3)) << 3);
            *(float4*)dst       = make_float4(p[0][cc], p[1][cc], p[2][cc], p[3][cc]);
            *(float4*)(dst + 4) = make_float4(p[4][cc], p[5][cc], p[6][cc], p[7][cc]);
            float* dst2 = Ps + (jB + cc) * PQ + ((tr ^ (tc & 3)) << 3);
            *(float4*)dst2       = make_float4(p[0][cc+4], p[1][cc+4], p[2][cc+4], p[3][cc+4]);
            *(float4*)(dst2 + 4) = make_float4(p[4][cc+4], p[5][cc+4], p[6][cc+4], p[7][cc+4]);
        }

        // write UNNORMALIZED p for non-diagonal tiles (fixed up in epilogue)
        if (jt < qt) {
#pragma unroll
            for (int r = 0; r < 8; r++) {
                float* wrow = Wb + (size_t)(qt * BQ + i0 + r) * S_LEN + jt * BQ;
                *(float4*)(wrow + jA) = make_float4(p[r][0], p[r][1], p[r][2], p[r][3]);
                *(float4*)(wrow + jB) = make_float4(p[r][4], p[r][5], p[r][6], p[r][7]);
            }
        }

        CPA_WAIT0();        // V(jt) landed
        __syncthreads();    // Ps + Vs visible; all QK reads of Ks[cur] done

        // K(jt+1) load into other buffer overlaps PV
        if (jt < qt) {
            cpasync_K(KTb + (size_t)(jt + 1) * BQ, sKs[cur ^ 1], tid);
            CPA_COMMIT();
        }

        // ---------------- PV: split j-range, 8x8 partials ----------------
#pragma unroll 4
        for (int jj = 0; jj < 64; jj++) {
            int j = jbase + jj;
            int keyp = (jj >> 2) & 3;
            const float* prow = Ps + j * PQ + ((tr ^ keyp) << 3);
            ulonglong2 a01 = *(const ulonglong2*)prow;
            ulonglong2 a23 = *(const ulonglong2*)(prow + 4);
            const float* vrow = Vs + j * PVP + ((((tc & 7) ^ (j & 7))) << 3);
            float4 b0 = *(const float4*)vrow;        // dd0..dd0+3
            float4 b1 = *(const float4*)(vrow + 4);  // dd0+4..dd0+7
            u64 aa[4] = {a01.x, a01.y, a23.x, a23.y};
            u64 bb[8] = {pk(b0.x,b0.x), pk(b0.y,b0.y), pk(b0.z,b0.z), pk(b0.w,b0.w),
                         pk(b1.x,b1.x), pk(b1.y,b1.y), pk(b1.z,b1.z), pk(b1.w,b1.w)};
#pragma unroll
            for (int rp = 0; rp < 4; rp++)
#pragma unroll
                for (int c = 0; c < 8; c++)
                    Oac[rp][c] = ffma2(aa[rp], bb[c], Oac[rp][c]);
        }

        CPA_WAIT0();        // K(jt+1) landed (overlapped with PV)
        __syncthreads();    // publish Ks[next]; all PV reads of Ps/Vs done
    }

    float invl[8];
#pragma unroll
    for (int r = 0; r < 8; r++) invl[r] = 1.0f / l_r[r];

    // diagonal tile: p still holds jt==qt values (m there == m_final) -> just /l
#pragma unroll
    for (int r = 0; r < 8; r++) {
        float* wrow = Wb + (size_t)(qt * BQ + i0 + r) * S_LEN + qt * BQ;
        *(float4*)(wrow + jA) = make_float4(p[r][0]*invl[r], p[r][1]*invl[r],
                                            p[r][2]*invl[r], p[r][3]*invl[r]);
        *(float4*)(wrow + jB) = make_float4(p[r][4]*invl[r], p[r][5]*invl[r],
                                            p[r][6]*invl[r], p[r][7]*invl[r]);
    }

    // ---------------- combine O partials across j-halves (Vs as scratch) ----------------
    if (tc >= 8) {
#pragma unroll
        for (int rp = 0; rp < 4; rp++) {
            float o0[8], o1[8];
#pragma unroll
            for (int c = 0; c < 8; c++) upk(Oac[rp][c], o0[c], o1[c]);
            float* s0 = Vs + (i0 + 2*rp)     * PVP + dd0;
            float* s1 = Vs + (i0 + 2*rp + 1) * PVP + dd0;
            *(float4*)s0       = make_float4(o0[0], o0[1], o0[2], o0[3]);
            *(float4*)(s0 + 4) = make_float4(o0[4], o0[5], o0[6], o0[7]);
            *(float4*)s1       = make_float4(o1[0], o1[1], o1[2], o1[3]);
            *(float4*)(s1 + 4) = make_float4(o1[4], o1[5], o1[6], o1[7]);
        }
    }
    __syncthreads();
    if (tc < 8) {
#pragma unroll
        for (int rp = 0; rp < 4; rp++) {
            float o0[8], o1[8];
#pragma unroll
            for (int c = 0; c < 8; c++) upk(Oac[rp][c], o0[c], o1[c]);
            const float* s0 = Vs + (i0 + 2*rp)     * PVP + dd0;
            const float* s1 = Vs + (i0 + 2*rp + 1) * PVP + dd0;
            float4 q0 = *(const float4*)s0, q1 = *(const float4*)(s0 + 4);
            float4 q2 = *(const float4*)s1, q3 = *(const float4*)(s1 + 4);
            float il0 = invl[2*rp], il1 = invl[2*rp+1];
            *(float4*)(Ob + (i0 + 2*rp) * D_DIM + dd0) =
                make_float4((o0[0]+q0.x)*il0, (o0[1]+q0.y)*il0, (o0[2]+q0.z)*il0, (o0[3]+q0.w)*il0);
            *(float4*)(Ob + (i0 + 2*rp) * D_DIM + dd0 + 4) =
                make_float4((o0[4]+q1.x)*il0, (o0[5]+q1.y)*il0, (o0[6]+q1.z)*il0, (o0[7]+q1.w)*il0);
            *(float4*)(Ob + (i0 + 2*rp + 1) * D_DIM + dd0) =
                make_float4((o1[0]+q2.x)*il1, (o1[1]+q2.y)*il1, (o1[2]+q2.z)*il1, (o1[3]+q2.w)*il1);
            *(float4*)(Ob + (i0 + 2*rp + 1) * D_DIM + dd0 + 4) =
                make_float4((o1[4]+q3.x)*il1, (o1[5]+q3.y)*il1, (o1[6]+q3.z)*il1, (o1[7]+q3.w)*il1);
        }
    }

    // ---------------- W fixup: rescale earlier tiles ----------------
    for (int jt = 0; jt < qt; jt++) {
#pragma unroll
        for (int r = 0; r < 8; r++) {
            float f = __expf(mh[jt * BQ + i0 + r] - m_r[r]) * invl[r];
            float* wrow = Wb + (size_t)(qt * BQ + i0 + r) * S_LEN + jt * BQ;
            float4 w0 = *(float4*)(wrow + jA);
            float4 w1 = *(float4*)(wrow + jB);
            w0.x *= f; w0.y *= f; w0.z *= f; w0.w *= f;
            w1.x *= f; w1.y *= f; w1.z *= f; w1.w *= f;
            *(float4*)(wrow + jA) = w0;
            *(float4*)(wrow + jB) = w1;
        }
    }

    // ---------------- zero-fill strict upper-triangle tiles ----------------
    float4 z = make_float4(0.f, 0.f, 0.f, 0.f);
    for (int jt = qt + 1; jt < NTQ; jt++) {
#pragma unroll
        for (int r = 0; r < 8; r++) {
            float* wrow = Wb + (size_t)(qt * BQ + i0 + r) * S_LEN + jt * BQ;
            *(float4*)(wrow + jA) = z;
            *(float4*)(wrow + jB) = z;
        }
    }
}

extern "C" void kernel_launch(void* const* d_in, const int* in_sizes, int n_in,
                              void* d_out, int out_size) {
    (void)in_sizes; (void)n_in; (void)out_size;
    const float* q = (const float*)d_in[0];
    const float* k = (const float*)d_in[1];
    const float* v = (const float*)d_in[2];
    // d_in[3] is the mask (tril ones) — causal structure applied analytically.

    float* out = (float*)d_out;
    float* Og  = out;                                   // [B,H,S,D]
    float* Wg  = out + (size_t)BH * S_LEN * D_DIM;      // [B,H,S,S]

    // pre-pass: K -> KT[bh][d][s]
    dim3 tg(S_LEN / 32, D_DIM / 32, BH);
    transpose_k_kernel<<<tg, 256>>>(k);

    cudaFuncSetAttribute(sdpa_causal_kernel,
                         cudaFuncAttributeMaxDynamicSharedMemorySize, SMEM_BYTES);

    dim3 grid(NTQ, BH);
    sdpa_causal_kernel<<<grid, NTHREADS, SMEM_BYTES>>>(q, v, Og, Wg);
}